// round 1
// baseline (speedup 1.0000x reference)
#include <cuda_runtime.h>
#include <cstdint>

#define Hs 96
#define Is 100
#define Ts 512
#define Bs 512
#define Gs 288               // 3*H
#define Ms (Ts*Bs)           // 262144 rows

// Scratch for input projections: [dir][m][g]  (604 MB static device array)
__device__ float g_xproj[2][Ms * Gs];

typedef unsigned long long u64;

__device__ __forceinline__ u64 fma2(u64 a, u64 b, u64 c) {
    u64 d;
    asm("fma.rn.f32x2 %0, %1, %2, %3;" : "=l"(d) : "l"(a), "l"(b), "l"(c));
    return d;
}
__device__ __forceinline__ float hsum2(u64 a) {
    float x, y;
    asm("mov.b64 {%0,%1}, %2;" : "=f"(x), "=f"(y) : "l"(a));
    return x + y;
}
__device__ __forceinline__ float sigm(float x) {
    return __fdividef(1.0f, 1.0f + __expf(-x));
}
__device__ __forceinline__ float tanh_(float x) {
    // tanh(x) = 1 - 2/(1+e^{2x}); safe at both infinities
    return 1.0f - __fdividef(2.0f, 1.0f + __expf(2.0f * x));
}

// ---------------------------------------------------------------------------
// Input projection: xproj[dir][m][g] = x[m,:] . w_ih[g,:] + b_ih[g]
// Tile: 64 rows x 48 cols, K=100 (50 f32x2 k-pairs). 256 threads, 4x3 per thread.
// ---------------------------------------------------------------------------
__global__ void proj_kernel(const float* __restrict__ x,
                            const float* __restrict__ wf, const float* __restrict__ bf,
                            const float* __restrict__ wb, const float* __restrict__ bb)
{
    __shared__ __align__(16) float xs[64][102];
    __shared__ __align__(16) float ws[48][102];

    const int dir = blockIdx.z;
    const float* __restrict__ w    = dir ? wb : wf;
    const float* __restrict__ bias = dir ? bb : bf;

    const size_t m0 = (size_t)blockIdx.x * 64;
    const int    g0 = blockIdx.y * 48;
    const int tid = threadIdx.x;

    // Coalesced tile loads (source regions are contiguous)
    const float* xsrc = x + m0 * Is;
    for (int i = tid; i < 64 * Is; i += 256) xs[i / Is][i % Is] = xsrc[i];
    const float* wsrc = w + (size_t)g0 * Is;
    for (int i = tid; i < 48 * Is; i += 256) ws[i / Is][i % Is] = wsrc[i];
    __syncthreads();

    const int cg = tid & 15;   // col group (consecutive tids -> consecutive cols)
    const int rg = tid >> 4;   // row group

    u64 acc[4][3];
    #pragma unroll
    for (int r = 0; r < 4; r++)
        #pragma unroll
        for (int c = 0; c < 3; c++) acc[r][c] = 0ull;

    #pragma unroll 10
    for (int k2 = 0; k2 < 50; k2++) {
        u64 xv[4], wv[3];
        #pragma unroll
        for (int r = 0; r < 4; r++)
            xv[r] = *(const u64*)&xs[rg * 4 + r][2 * k2];
        #pragma unroll
        for (int c = 0; c < 3; c++)
            wv[c] = *(const u64*)&ws[cg + 16 * c][2 * k2];
        #pragma unroll
        for (int r = 0; r < 4; r++)
            #pragma unroll
            for (int c = 0; c < 3; c++)
                acc[r][c] = fma2(xv[r], wv[c], acc[r][c]);
    }

    #pragma unroll
    for (int c = 0; c < 3; c++) {
        const int gcol = g0 + cg + 16 * c;
        const float bv = __ldg(&bias[gcol]);
        #pragma unroll
        for (int r = 0; r < 4; r++) {
            const size_t m = m0 + rg * 4 + r;
            g_xproj[dir][m * Gs + gcol] = hsum2(acc[r][c]) + bv;
        }
    }
}

// ---------------------------------------------------------------------------
// Recurrent scan: 128 CTAs (64 batch-groups x 2 dirs), 288 threads,
// 8 batch elements per CTA. Thread g holds W_hh[g,:] in 48 u64 registers.
// ---------------------------------------------------------------------------
__global__ __launch_bounds__(288, 1) void scan_kernel(
    const float* __restrict__ whf, const float* __restrict__ bhf,
    const float* __restrict__ whb, const float* __restrict__ bhb,
    float* __restrict__ out)
{
    __shared__ __align__(16) float hsh[8][Hs];   // current hidden state (single buffer)
    __shared__ float pre[8][2 * Hs];             // pre-activations for r,z
    __shared__ float hpn[8][Hs];                 // hp for n-gate
    __shared__ float xpn[8][Hs];                 // xp for n-gate

    const int tid = threadIdx.x;                 // gate row g in [0,288)
    const int dir = blockIdx.x >> 6;
    const int b0  = (blockIdx.x & 63) * 8;

    const float* __restrict__ wh = dir ? whb : whf;
    const float* __restrict__ bh = dir ? bhb : bhf;

    // W_hh row -> registers (row is 384B, 8-byte aligned)
    u64 w2[48];
    {
        const u64* wrow = (const u64*)(wh + tid * Hs);
        #pragma unroll
        for (int j = 0; j < 48; j++) w2[j] = __ldg(&wrow[j]);
    }
    const float bhv = __ldg(&bh[tid]);

    // h0 = 0
    for (int i = tid; i < 8 * Hs; i += 288) (&hsh[0][0])[i] = 0.0f;

    const float* __restrict__ xpbase = g_xproj[dir];
    const int t_first = dir ? (Ts - 1) : 0;
    const int tstep   = dir ? -1 : 1;

    float xp_cur[8], xp_nxt[8];
    #pragma unroll
    for (int bb = 0; bb < 8; bb++)
        xp_cur[bb] = __ldg(&xpbase[((size_t)t_first * Bs + b0 + bb) * Gs + tid]);

    __syncthreads();

    int tt = t_first;
    #pragma unroll 1
    for (int t = 0; t < Ts; t++) {
        // Prefetch next step's xp while the matvec runs
        int tn = (t == Ts - 1) ? tt : (tt + tstep);
        #pragma unroll
        for (int bb = 0; bb < 8; bb++)
            xp_nxt[bb] = __ldg(&xpbase[((size_t)tn * Bs + b0 + bb) * Gs + tid]);

        // Stage 1: hp[g] = W_hh[g,:] . h[b]  for 8 batches (f32x2, k in pairs)
        u64 acc[8];
        #pragma unroll
        for (int bb = 0; bb < 8; bb++) acc[bb] = 0ull;
        #pragma unroll
        for (int j = 0; j < 24; j++) {
            #pragma unroll
            for (int bb = 0; bb < 8; bb++) {
                ulonglong2 hv = *(const ulonglong2*)&hsh[bb][4 * j];  // LDS.128 broadcast
                acc[bb] = fma2(w2[2 * j],     hv.x, acc[bb]);
                acc[bb] = fma2(w2[2 * j + 1], hv.y, acc[bb]);
            }
        }

        // Stage 2: publish pre-activations
        #pragma unroll
        for (int bb = 0; bb < 8; bb++) {
            const float hpv = hsum2(acc[bb]) + bhv;
            if (tid < 2 * Hs) {
                pre[bb][tid] = xp_cur[bb] + hpv;
            } else {
                hpn[bb][tid - 2 * Hs] = hpv;
                xpn[bb][tid - 2 * Hs] = xp_cur[bb];
            }
        }
        __syncthreads();

        // Stage 3: gates + state update. 768 elements over 256 threads (3 each).
        if (tid < 256) {
            #pragma unroll
            for (int e3 = 0; e3 < 3; e3++) {
                const int e  = tid * 3 + e3;
                const int bb = e / Hs;
                const int i  = e - bb * Hs;
                const float r = sigm(pre[bb][i]);
                const float z = sigm(pre[bb][Hs + i]);
                const float n = tanh_(fmaf(r, hpn[bb][i], xpn[bb][i]));
                const float hold = hsh[bb][i];
                const float hnew = fmaf(z, hold - n, n);
                hsh[bb][i] = hnew;
                out[((size_t)tt * Bs + b0 + bb) * (2 * Hs) + dir * Hs + i] = hnew;
            }
        }
        __syncthreads();

        #pragma unroll
        for (int bb = 0; bb < 8; bb++) xp_cur[bb] = xp_nxt[bb];
        tt += tstep;
    }
}

// ---------------------------------------------------------------------------
extern "C" void kernel_launch(void* const* d_in, const int* in_sizes, int n_in,
                              void* d_out, int out_size)
{
    const float* x      = (const float*)d_in[0];
    const float* w_ih_f = (const float*)d_in[1];
    const float* w_hh_f = (const float*)d_in[2];
    const float* b_ih_f = (const float*)d_in[3];
    const float* b_hh_f = (const float*)d_in[4];
    const float* w_ih_b = (const float*)d_in[5];
    const float* w_hh_b = (const float*)d_in[6];
    const float* b_ih_b = (const float*)d_in[7];
    const float* b_hh_b = (const float*)d_in[8];
    float* out = (float*)d_out;

    dim3 pg(Ms / 64, Gs / 48, 2);     // (4096, 6, 2)
    proj_kernel<<<pg, 256>>>(x, w_ih_f, b_ih_f, w_ih_b, b_ih_b);
    scan_kernel<<<128, 288>>>(w_hh_f, b_hh_f, w_hh_b, b_hh_b, out);
}